// round 14
// baseline (speedup 1.0000x reference)
#include <cuda_runtime.h>
#include <cuda_bf16.h>

#define BATCH 1024
#define EMB 128
#define CBK 1024

typedef unsigned long long ull;

// packed f32x2 helpers: each lane is an independent exact fp32 RN op
__device__ __forceinline__ ull pk2(float lo, float hi)
{
    ull r; asm("mov.b64 %0,{%1,%2};" : "=l"(r) : "f"(lo), "f"(hi)); return r;
}
__device__ __forceinline__ void upk2(ull v, float& lo, float& hi)
{
    asm("mov.b64 {%0,%1},%2;" : "=f"(lo), "=f"(hi) : "l"(v));
}
__device__ __forceinline__ void fma2(ull& d, ull a, ull b)
{
    asm("fma.rn.f32x2 %0, %1, %2, %0;" : "+l"(d) : "l"(a), "l"(b));
}

// ---------------- scratch (static device globals; no runtime alloc) ----------
__device__ float         g_p1[BATCH * 32 * 100];     // pooled conv1 [b][32][10][10]
__device__ unsigned char g_i1[BATCH * 32 * 100];
__device__ float         g_z [BATCH * 96 * 25];      // pooled conv2 [b][96][5][5]
__device__ unsigned char g_i2[BATCH * 96 * 25];
__device__ float         g_vq[BATCH * EMB * 25];     // pre-VQ tokens
__device__ int           g_ind[BATCH * EMB];         // argmin indices
__device__ float         g_lat[BATCH * 96 * 25];     // latent / feat
__device__ float         g_d1[BATCH * 32 * 100];     // decoder conv1 out
__device__ float         g_part[148];                // loss partials
__device__ float         g_wc2[27648];               // conv2 w relaid [kk][ci][c]
__device__ float         g_wd1[27648];               // dec1  w relaid [kk][ci][c]

// ---------------- K0: one-off weight relayout (c-fastest) -------------------
__global__ void k_prep(const float* __restrict__ w2, const float* __restrict__ wd)
{
    int i = blockIdx.x * 512 + threadIdx.x;
    if (i < 27648) {
        {   // conv2: w2[c][ci][kk], c<96, ci<32, kk<9  ->  [kk][ci][c]
            int c = i / 288, r = i % 288;
            int ci = r / 9, kk = r % 9;
            g_wc2[(kk * 32 + ci) * 96 + c] = w2[i];
        }
        {   // dec1: wd[c][ci][kk], c<32, ci<96, kk<9  ->  [kk][ci][c]
            int c = i / 864, r = i % 864;
            int ci = r / 9, kk = r % 9;
            g_wd1[(kk * 96 + ci) * 32 + c] = wd[i];
        }
    }
}

// ---------------- K1: conv1(3->32,3x3,pad1)+relu+pool2x2 --------------------
__global__ void k_conv1_pool(const float* __restrict__ x, const float* __restrict__ w,
                             const float* __restrict__ bias)
{
    __shared__ float sx[3 * 20 * 20];
    __shared__ float sw[32 * 27];
    __shared__ float sb[32];
    int b = blockIdx.x;
    const float* xi = x + b * 1200;
    for (int i = threadIdx.x; i < 1200; i += 512) sx[i] = xi[i];
    for (int i = threadIdx.x; i < 864;  i += 512) sw[i] = w[i];
    if (threadIdx.x < 32) sb[threadIdx.x] = bias[threadIdx.x];
    __syncthreads();
    for (int t = threadIdx.x; t < 3200; t += 512) {
        int c = t / 100, pp = t % 100;
        int ph = pp / 10, pw = pp % 10;
        float best = -3.4e38f; int bi = 0;
        #pragma unroll
        for (int d = 0; d < 4; d++) {
            int oh = 2 * ph + (d >> 1), ow = 2 * pw + (d & 1);
            float acc = 0.f;
            #pragma unroll
            for (int ky = 0; ky < 3; ky++) {
                int iy = oh + ky - 1;
                if ((unsigned)iy < 20u) {
                    #pragma unroll
                    for (int kx = 0; kx < 3; kx++) {
                        int ix = ow + kx - 1;
                        if ((unsigned)ix < 20u) {
                            #pragma unroll
                            for (int ci = 0; ci < 3; ci++)
                                acc = fmaf(sx[ci * 400 + iy * 20 + ix],
                                           sw[c * 27 + ci * 9 + ky * 3 + kx], acc);
                        }
                    }
                }
            }
            float v = fmaxf(__fadd_rn(acc, sb[c]), 0.f);
            if (v > best) { best = v; bi = d; }   // first-max tie-break
        }
        g_p1[b * 3200 + t] = best;
        g_i1[b * 3200 + t] = (unsigned char)bi;
    }
}

// ---------------- K2: conv2(32->96,3x3,pad1)+relu+pool2x2, f32x2 ------------
// x dup-pairs {x,x} in smem [pos][33ci-padded]; w smem c-fastest [kk][ci][96c].
// acc lanes = (u, u+1); per-output chain (ky,kx,ci) ascending — bit-identical.
__global__ void k_conv2_pool(const float* __restrict__ bias)
{
    extern __shared__ char smraw2[];
    ull*   sx = (ull*)smraw2;                      // 4752 pairs  (38016 B)
    float* sw = (float*)(smraw2 + 38016);          // 27648 f     (110592 B)
    float* sb = sw + 27648;                        // 96
    int b = blockIdx.x;
    const float* pin = g_p1 + b * 3200;
    for (int i = threadIdx.x; i < 144 * 32; i += 512) {
        int pos = i / 32, ci = i % 32;
        int iy = pos / 12 - 1, ix = pos % 12 - 1;
        float v = ((unsigned)iy < 10u && (unsigned)ix < 10u)
                ? pin[ci * 100 + iy * 10 + ix] : 0.f;
        sx[pos * 33 + ci] = pk2(v, v);
    }
    for (int i = threadIdx.x; i < 27648; i += 512) sw[i] = g_wc2[i];  // linear
    for (int i = threadIdx.x; i < 96; i += 512) sb[i] = bias[i];
    __syncthreads();
    for (int t = threadIdx.x; t < 600; t += 512) {
        int cg = t / 25, pp = t % 25;
        int ph = pp / 5, pw_ = pp % 5;
        ull ap[4][2];
        #pragma unroll
        for (int d = 0; d < 4; d++) { ap[d][0] = 0ULL; ap[d][1] = 0ULL; }
        #pragma unroll
        for (int ky = 0; ky < 3; ky++) {
            #pragma unroll
            for (int kx = 0; kx < 3; kx++) {
                int base = ((2 * ph + ky) * 12 + (2 * pw_ + kx)) * 33;
                const float* wr = sw + (ky * 3 + kx) * 32 * 96 + cg * 4;
                for (int ci = 0; ci < 32; ci++) {
                    ull x0 = sx[base + ci],       x1 = sx[base + 33 + ci];
                    ull x2 = sx[base + 396 + ci], x3 = sx[base + 429 + ci];
                    float4 wq = *reinterpret_cast<const float4*>(wr + ci * 96);
                    ull w01 = ((const ull*)&wq)[0];
                    ull w23 = ((const ull*)&wq)[1];
                    fma2(ap[0][0], x0, w01); fma2(ap[0][1], x0, w23);
                    fma2(ap[1][0], x1, w01); fma2(ap[1][1], x1, w23);
                    fma2(ap[2][0], x2, w01); fma2(ap[2][1], x2, w23);
                    fma2(ap[3][0], x3, w01); fma2(ap[3][1], x3, w23);
                }
            }
        }
        float acc[4][4];
        #pragma unroll
        for (int d = 0; d < 4; d++) {
            upk2(ap[d][0], acc[d][0], acc[d][1]);
            upk2(ap[d][1], acc[d][2], acc[d][3]);
        }
        #pragma unroll
        for (int u = 0; u < 4; u++) {
            int c = cg * 4 + u;
            float best = -3.4e38f; int bi = 0;
            #pragma unroll
            for (int d = 0; d < 4; d++) {
                float v = fmaxf(__fadd_rn(acc[d][u], sb[c]), 0.f);
                if (v > best) { best = v; bi = d; }
            }
            g_z [b * 2400 + c * 25 + pp] = best;
            g_i2[b * 2400 + c * 25 + pp] = (unsigned char)bi;
        }
    }
}

// ---------------- K3: pre-VQ 1x1 conv 96->128 (seq over c, bias after) ------
__global__ void k_pre(const float* __restrict__ w, const float* __restrict__ bias)
{
    extern __shared__ float sm3[];
    float* sz = sm3;            // 2400
    float* sw = sm3 + 2400;     // 12288
    float* sb = sw + 12288;     // 128
    int b = blockIdx.x;
    const float* zin = g_z + b * 2400;
    for (int i = threadIdx.x; i < 2400;  i += 512) sz[i] = zin[i];
    for (int i = threadIdx.x; i < 12288; i += 512) sw[i] = w[i];
    for (int i = threadIdx.x; i < 128;   i += 512) sb[i] = bias[i];
    __syncthreads();
    for (int t = threadIdx.x; t < 800; t += 512) {
        int eg = t / 25, pp = t % 25;
        float a0 = 0.f, a1 = 0.f, a2 = 0.f, a3 = 0.f;
        for (int c = 0; c < 96; c++) {
            float zv = sz[c * 25 + pp];
            a0 = fmaf(zv, sw[(eg * 4 + 0) * 96 + c], a0);
            a1 = fmaf(zv, sw[(eg * 4 + 1) * 96 + c], a1);
            a2 = fmaf(zv, sw[(eg * 4 + 2) * 96 + c], a2);
            a3 = fmaf(zv, sw[(eg * 4 + 3) * 96 + c], a3);
        }
        g_vq[b * 3200 + (eg * 4 + 0) * 25 + pp] = __fadd_rn(a0, sb[eg * 4 + 0]);
        g_vq[b * 3200 + (eg * 4 + 1) * 25 + pp] = __fadd_rn(a1, sb[eg * 4 + 1]);
        g_vq[b * 3200 + (eg * 4 + 2) * 25 + pp] = __fadd_rn(a2, sb[eg * 4 + 2]);
        g_vq[b * 3200 + (eg * 4 + 3) * 25 + pp] = __fadd_rn(a3, sb[eg * 4 + 3]);
    }
}

// ---------------- K5: VQ argmin + commit loss, f32x2 (2 tokens = lo/hi) -----
// Codebook in smem as duplicated pairs {c,c}: row = 26 pairs (208 B, 16B-align).
// Per-token chain: fn mul/add seq; dot = seq-k fma (lane-exact); d = (fn-2dot)+cn;
// first-min ascending j. Identical FP sequence to the R12 passing kernel.
__global__ void k_vq(const float* __restrict__ cb)
{
    extern __shared__ char smraw5[];
    ull*   scb2 = (ull*)smraw5;                    // 1024*26 pairs (212992 B)
    float* scn  = (float*)(smraw5 + 212992);       // 1024
    float* sred = scn + 1024;                      // 512
    for (int i = threadIdx.x; i < 1024 * 25; i += 512) {
        int j = i / 25, k = i % 25;
        float v = cb[i];
        scb2[j * 26 + k] = pk2(v, v);
    }
    for (int j = threadIdx.x; j < 1024; j += 512) scb2[j * 26 + 25] = 0ULL;
    __syncthreads();
    // codebook norms: mul-then-add, seq ascending k
    for (int j = threadIdx.x; j < 1024; j += 512) {
        float s = 0.f;
        for (int k = 0; k < 25; k++) {
            float v = cb[j * 25 + k];
            s = __fadd_rn(s, __fmul_rn(v, v));
        }
        scn[j] = s;
    }
    __syncthreads();

    int start = (int)(((long long)blockIdx.x * 131072) / 148);
    int end   = (int)(((long long)(blockIdx.x + 1) * 131072) / 148);
    int count = end - start;                  // 885 or 886
    int tid = threadIdx.x;
    bool v0 = tid < count;
    bool v1 = tid + 512 < count;
    int t0 = start + (v0 ? tid : 0);
    int t1 = start + (v1 ? tid + 512 : 0);

    ull fpair[25];
    float fn0 = 0.f, fn1 = 0.f;
    {
        const float* fp0 = g_vq + t0 * 25;
        const float* fp1 = g_vq + t1 * 25;
        #pragma unroll
        for (int k = 0; k < 25; k++) {
            float a = fp0[k], b = fp1[k];
            fn0 = __fadd_rn(fn0, __fmul_rn(a, a));
            fn1 = __fadd_rn(fn1, __fmul_rn(b, b));
            fpair[k] = pk2(a, b);
        }
    }
    float best0 = 3.4e38f, best1 = 3.4e38f;
    int bj0 = 0, bj1 = 0;
    for (int j = 0; j < 1024; j++) {
        const ulonglong2* row = (const ulonglong2*)(scb2 + j * 26);
        ull dot = 0ULL;
        #pragma unroll
        for (int kk = 0; kk < 12; kk++) {
            ulonglong2 q = row[kk];
            fma2(dot, q.x, fpair[2 * kk]);
            fma2(dot, q.y, fpair[2 * kk + 1]);
        }
        fma2(dot, ((const ull*)row)[24], fpair[24]);
        float dot0, dot1;
        upk2(dot, dot0, dot1);
        float cnj = scn[j];
        float d0 = __fadd_rn(__fsub_rn(fn0, 2.f * dot0), cnj);
        float d1 = __fadd_rn(__fsub_rn(fn1, 2.f * dot1), cnj);
        if (d0 < best0) { best0 = d0; bj0 = j; }
        if (d1 < best1) { best1 = d1; bj1 = j; }
    }
    float lsum = 0.f;
    const float* scbf = (const float*)scb2;   // lo lane = codebook value
    if (v0) {
        g_ind[t0] = bj0;
        const float* fp = g_vq + t0 * 25;
        #pragma unroll
        for (int k = 0; k < 25; k++) {
            float df = scbf[(bj0 * 26 + k) * 2] - fp[k];
            lsum = fmaf(df, df, lsum);
        }
    }
    if (v1) {
        g_ind[t1] = bj1;
        const float* fp = g_vq + t1 * 25;
        #pragma unroll
        for (int k = 0; k < 25; k++) {
            float df = scbf[(bj1 * 26 + k) * 2] - fp[k];
            lsum = fmaf(df, df, lsum);
        }
    }
    sred[tid] = lsum;
    __syncthreads();
    for (int s = 256; s > 0; s >>= 1) {
        if (tid < s) sred[tid] += sred[tid + s];
        __syncthreads();
    }
    if (tid == 0) g_part[blockIdx.x] = sred[0];
}

// ---------------- K6: gather + transpose-conv 1x1 (128->96), bias after -----
__global__ void k_trans(const float* __restrict__ cb, const float* __restrict__ w,
                        const float* __restrict__ bias)
{
    extern __shared__ float sm6[];
    float* szr = sm6;            // 128*25
    float* sw  = sm6 + 3200;     // 12288
    float* sb  = sw + 12288;     // 96
    int b = blockIdx.x;
    for (int t = threadIdx.x; t < 3200; t += 512) {
        int i = t / 25, p = t % 25;
        szr[t] = cb[g_ind[b * 128 + i] * 25 + p];
    }
    for (int i = threadIdx.x; i < 12288; i += 512) sw[i] = w[i];
    for (int i = threadIdx.x; i < 96;    i += 512) sb[i] = bias[i];
    __syncthreads();
    for (int t = threadIdx.x; t < 600; t += 512) {
        int og = t / 25, pp = t % 25;
        float a0 = 0.f, a1 = 0.f, a2 = 0.f, a3 = 0.f;
        for (int i = 0; i < 128; i++) {
            float zv = szr[i * 25 + pp];
            const float* wr = sw + i * 96 + og * 4;
            a0 = fmaf(zv, wr[0], a0);
            a1 = fmaf(zv, wr[1], a1);
            a2 = fmaf(zv, wr[2], a2);
            a3 = fmaf(zv, wr[3], a3);
        }
        g_lat[b * 2400 + (og * 4 + 0) * 25 + pp] = __fadd_rn(a0, sb[og * 4 + 0]);
        g_lat[b * 2400 + (og * 4 + 1) * 25 + pp] = __fadd_rn(a1, sb[og * 4 + 1]);
        g_lat[b * 2400 + (og * 4 + 2) * 25 + pp] = __fadd_rn(a2, sb[og * 4 + 2]);
        g_lat[b * 2400 + (og * 4 + 3) * 25 + pp] = __fadd_rn(a3, sb[og * 4 + 3]);
    }
}

// ---------------- K7: unpool(idx2) + dec1 conv(96->32)+relu, f32x2 ----------
// x dup-pairs in smem; weights via __ldg float4 from g_wd1 [kk][ci][32c].
// ci-halves split + smem partial reduction (dec1 is order-free downstream).
__global__ void k_dec1(const float* __restrict__ bias)
{
    extern __shared__ char smraw7[];
    ull*   su = (ull*)smraw7;                      // 144*97 pairs (111744 B)
    float* sp = (float*)(smraw7 + 111744);         // 200*16 partials (12800 B)
    float* sb = sp + 3200;                         // 32
    int b = blockIdx.x;
    for (int i = threadIdx.x; i < 13968; i += 512) su[i] = 0ULL;
    if (threadIdx.x < 32) sb[threadIdx.x] = bias[threadIdx.x];
    __syncthreads();
    for (int t = threadIdx.x; t < 2400; t += 512) {
        int c = t / 25, pp = t % 25;
        int ph = pp / 5, pw_ = pp % 5;
        int d = g_i2[b * 2400 + t];
        int y = 2 * ph + (d >> 1), x = 2 * pw_ + (d & 1);
        float v = g_lat[b * 2400 + t];
        su[((y + 1) * 12 + (x + 1)) * 97 + c] = pk2(v, v);
    }
    __syncthreads();
    int tid = threadIdx.x;
    bool active = tid < 400;
    int cg = 0, win = 0, half = 0;
    float acc[4][4];
    if (active) {
        cg = tid / 50;
        int rem = tid % 50;
        half = rem / 25;
        win = rem % 25;
        int sy = win / 5, sx_ = win % 5;
        int cibase = half * 48;
        ull ap[4][2];
        #pragma unroll
        for (int d = 0; d < 4; d++) { ap[d][0] = 0ULL; ap[d][1] = 0ULL; }
        #pragma unroll
        for (int ky = 0; ky < 3; ky++) {
            #pragma unroll
            for (int kx = 0; kx < 3; kx++) {
                int base = ((2 * sy + ky) * 12 + (2 * sx_ + kx)) * 97 + cibase;
                const float* wg = g_wd1 + ((ky * 3 + kx) * 96 + cibase) * 32 + cg * 4;
                for (int ci = 0; ci < 48; ci++) {
                    ull x0 = su[base + ci],        x1 = su[base + 97 + ci];
                    ull x2 = su[base + 1164 + ci], x3 = su[base + 1261 + ci];
                    float4 wq = __ldg(reinterpret_cast<const float4*>(wg + ci * 32));
                    ull w01 = ((const ull*)&wq)[0];
                    ull w23 = ((const ull*)&wq)[1];
                    fma2(ap[0][0], x0, w01); fma2(ap[0][1], x0, w23);
                    fma2(ap[1][0], x1, w01); fma2(ap[1][1], x1, w23);
                    fma2(ap[2][0], x2, w01); fma2(ap[2][1], x2, w23);
                    fma2(ap[3][0], x3, w01); fma2(ap[3][1], x3, w23);
                }
            }
        }
        #pragma unroll
        for (int d = 0; d < 4; d++) {
            upk2(ap[d][0], acc[d][0], acc[d][1]);
            upk2(ap[d][1], acc[d][2], acc[d][3]);
        }
        if (half == 1) {
            float* pp_ = sp + (cg * 25 + win) * 16;
            #pragma unroll
            for (int d = 0; d < 4; d++)
                #pragma unroll
                for (int u = 0; u < 4; u++) pp_[d * 4 + u] = acc[d][u];
        }
    }
    __syncthreads();
    if (active && half == 0) {
        int sy = win / 5, sx_ = win % 5;
        const float* pp_ = sp + (cg * 25 + win) * 16;
        #pragma unroll
        for (int d = 0; d < 4; d++) {
            int oy = 2 * sy + (d >> 1), ox = 2 * sx_ + (d & 1);
            #pragma unroll
            for (int u = 0; u < 4; u++) {
                float tot = acc[d][u] + pp_[d * 4 + u];
                g_d1[b * 3200 + (cg * 4 + u) * 100 + oy * 10 + ox] =
                    fmaxf(__fadd_rn(tot, sb[cg * 4 + u]), 0.f);
            }
        }
    }
}

// ---------------- K8: unpool(idx1) + dec2 conv(32->3) -> r_x ----------------
__global__ void k_dec2(const float* __restrict__ w, const float* __restrict__ bias,
                       float* __restrict__ rx)
{
    extern __shared__ float sm8[];
    float* su = sm8;             // 484*33 = 15972
    float* sw = sm8 + 15972;     // 864
    float* sb = sw + 864;        // 3
    int b = blockIdx.x;
    for (int i = threadIdx.x; i < 15972; i += 512) su[i] = 0.f;
    for (int i = threadIdx.x; i < 864; i += 512) {
        int c = i / 288, r = i % 288;
        int ci = r / 9, kk = r % 9;
        sw[c * 288 + kk * 32 + ci] = w[i];
    }
    if (threadIdx.x < 3) sb[threadIdx.x] = bias[threadIdx.x];
    __syncthreads();
    for (int t = threadIdx.x; t < 3200; t += 512) {
        int c = t / 100, pp = t % 100;
        int ph = pp / 10, pw_ = pp % 10;
        int d = g_i1[b * 3200 + t];
        int y = 2 * ph + (d >> 1), x = 2 * pw_ + (d & 1);
        su[((y + 1) * 22 + (x + 1)) * 33 + c] = g_d1[b * 3200 + t];
    }
    __syncthreads();
    for (int t = threadIdx.x; t < 100; t += 512) {
        int sy = t / 10, sx_ = t % 10;
        float acc[4][3];
        #pragma unroll
        for (int d = 0; d < 4; d++)
            #pragma unroll
            for (int u = 0; u < 3; u++) acc[d][u] = 0.f;
        #pragma unroll
        for (int ky = 0; ky < 3; ky++) {
            #pragma unroll
            for (int kx = 0; kx < 3; kx++) {
                int base = ((2 * sy + ky) * 22 + (2 * sx_ + kx)) * 33;
                const float* wr = sw + (ky * 3 + kx) * 32;
                for (int ci = 0; ci < 32; ci++) {
                    float x0 = su[base + ci], x1 = su[base + 33 + ci];
                    float x2 = su[base + 726 + ci], x3 = su[base + 759 + ci];
                    #pragma unroll
                    for (int u = 0; u < 3; u++) {
                        float wv = wr[u * 288 + ci];
                        acc[0][u] = fmaf(x0, wv, acc[0][u]);
                        acc[1][u] = fmaf(x1, wv, acc[1][u]);
                        acc[2][u] = fmaf(x2, wv, acc[2][u]);
                        acc[3][u] = fmaf(x3, wv, acc[3][u]);
                    }
                }
            }
        }
        #pragma unroll
        for (int d = 0; d < 4; d++) {
            int oy = 2 * sy + (d >> 1), ox = 2 * sx_ + (d & 1);
            #pragma unroll
            for (int u = 0; u < 3; u++)
                rx[b * 1200 + u * 400 + oy * 20 + ox] = __fadd_rn(acc[d][u], sb[u]);
        }
    }
}

// ---------------- K9: pose head + loss finalize -----------------------------
__global__ void k_pose(const float* __restrict__ w1, const float* __restrict__ b1,
                       const float* __restrict__ w2, const float* __restrict__ b2,
                       float* __restrict__ kp, float* __restrict__ out0)
{
    __shared__ float hid[8][32];
    __shared__ float sw2[32 * 36];
    int b0 = blockIdx.x * 8;
    int bl = threadIdx.x >> 5, j = threadIdx.x & 31;
    for (int i = threadIdx.x; i < 1152; i += 256) sw2[i] = w2[i];
    const float* fp = g_lat + (b0 + bl) * 2400;
    float a = 0.f;
    for (int k = 0; k < 2400; k++)
        a = fmaf(fp[k], w1[k * 32 + j], a);
    hid[bl][j] = fmaxf(__fadd_rn(a, b1[j]), 0.f);
    __syncthreads();
    for (int t = threadIdx.x; t < 288; t += 256) {
        int bb = t / 36, m = t % 36;
        float a2 = 0.f;
        #pragma unroll
        for (int jj = 0; jj < 32; jj++)
            a2 = fmaf(hid[bb][jj], sw2[jj * 36 + m], a2);
        kp[(b0 + bb) * 36 + m] = __fadd_rn(a2, b2[m]);
    }
    if (blockIdx.x == 0 && threadIdx.x == 0) {
        float s = 0.f;
        #pragma unroll 8
        for (int i = 0; i < 148; i++) s += g_part[i];
        out0[0] = 0.25f * s / 3276800.f;
    }
}

// ---------------- launch ----------------------------------------------------
extern "C" void kernel_launch(void* const* d_in, const int* in_sizes, int n_in,
                              void* d_out, int out_size)
{
    const float* x      = (const float*)d_in[0];
    const float* e1w    = (const float*)d_in[1];
    const float* e1b    = (const float*)d_in[2];
    const float* e2w    = (const float*)d_in[3];
    const float* e2b    = (const float*)d_in[4];
    const float* prew   = (const float*)d_in[5];
    const float* preb   = (const float*)d_in[6];
    const float* cb     = (const float*)d_in[7];
    const float* tw     = (const float*)d_in[8];
    const float* tb     = (const float*)d_in[9];
    const float* d1w    = (const float*)d_in[10];
    const float* d1b    = (const float*)d_in[11];
    const float* d2w    = (const float*)d_in[12];
    const float* d2b    = (const float*)d_in[13];
    const float* hw1    = (const float*)d_in[14];
    const float* hb1    = (const float*)d_in[15];
    const float* hw2    = (const float*)d_in[16];
    const float* hb2    = (const float*)d_in[17];
    float* out = (float*)d_out;

    const int SM2 = 38016 + 110592 + 384;                 // 149, conv2 bytes
    const int SM3 = (2400 + 12288 + 128) * 4;             // 59264
    const int SM5 = 212992 + 4096 + 2048;                 // 219136 (vq)
    const int SM6 = (3200 + 12288 + 96) * 4;              // 62336
    const int SM7 = 111744 + 12800 + 128;                 // 124672 (dec1)
    const int SM8 = (15972 + 864 + 4) * 4;                // 67360

    cudaFuncSetAttribute(k_conv2_pool, cudaFuncAttributeMaxDynamicSharedMemorySize, SM2);
    cudaFuncSetAttribute(k_pre,        cudaFuncAttributeMaxDynamicSharedMemorySize, SM3);
    cudaFuncSetAttribute(k_vq,         cudaFuncAttributeMaxDynamicSharedMemorySize, SM5);
    cudaFuncSetAttribute(k_trans,      cudaFuncAttributeMaxDynamicSharedMemorySize, SM6);
    cudaFuncSetAttribute(k_dec1,       cudaFuncAttributeMaxDynamicSharedMemorySize, SM7);
    cudaFuncSetAttribute(k_dec2,       cudaFuncAttributeMaxDynamicSharedMemorySize, SM8);

    float* rx = out + 1;                 // [1024,3,20,20]
    float* kp = out + 1 + 1228800;       // [1024,36]

    k_prep<<<54, 512>>>(e2w, d1w);
    k_conv1_pool<<<BATCH, 512>>>(x, e1w, e1b);
    k_conv2_pool<<<BATCH, 512, SM2>>>(e2b);
    k_pre<<<BATCH, 512, SM3>>>(prew, preb);
    k_vq<<<148, 512, SM5>>>(cb);
    k_trans<<<BATCH, 512, SM6>>>(cb, tw, tb);
    k_dec1<<<BATCH, 512, SM7>>>(d1b);
    k_dec2<<<BATCH, 512, SM8>>>(d2w, d2b, rx);
    k_pose<<<128, 256>>>(hw1, hb1, hw2, hb2, kp, out);
}

// round 16
// speedup vs baseline: 1.3740x; 1.3740x over previous
#include <cuda_runtime.h>
#include <cuda_bf16.h>

#define BATCH 1024
#define EMB 128
#define CBK 1024

// ---------------- scratch (static device globals; no runtime alloc) ----------
__device__ float         g_p1[BATCH * 32 * 100];     // pooled conv1 [b][32][10][10]
__device__ unsigned char g_i1[BATCH * 32 * 100];
__device__ float         g_z [BATCH * 96 * 25];      // pooled conv2 [b][96][5][5]
__device__ unsigned char g_i2[BATCH * 96 * 25];
__device__ float         g_vq[BATCH * EMB * 25];     // pre-VQ tokens
__device__ int           g_ind[BATCH * EMB];         // argmin indices
__device__ float         g_lat[BATCH * 96 * 25];     // latent / feat
__device__ float         g_d1[BATCH * 32 * 100];     // decoder conv1 out
__device__ float         g_part[148];                // loss partials

// ---------------- K1: conv1(3->32,3x3,pad1)+relu+pool2x2 (640thr: 5 items) --
__global__ void k_conv1_pool(const float* __restrict__ x, const float* __restrict__ w,
                             const float* __restrict__ bias)
{
    __shared__ float sx[3 * 20 * 20];
    __shared__ float sw[32 * 27];
    __shared__ float sb[32];
    int b = blockIdx.x;
    const float* xi = x + b * 1200;
    for (int i = threadIdx.x; i < 1200; i += 640) sx[i] = xi[i];
    for (int i = threadIdx.x; i < 864;  i += 640) sw[i] = w[i];
    if (threadIdx.x < 32) sb[threadIdx.x] = bias[threadIdx.x];
    __syncthreads();
    for (int t = threadIdx.x; t < 3200; t += 640) {
        int c = t / 100, pp = t % 100;
        int ph = pp / 10, pw = pp % 10;
        float best = -3.4e38f; int bi = 0;
        #pragma unroll
        for (int d = 0; d < 4; d++) {
            int oh = 2 * ph + (d >> 1), ow = 2 * pw + (d & 1);
            float acc = 0.f;
            #pragma unroll
            for (int ky = 0; ky < 3; ky++) {
                int iy = oh + ky - 1;
                if ((unsigned)iy < 20u) {
                    #pragma unroll
                    for (int kx = 0; kx < 3; kx++) {
                        int ix = ow + kx - 1;
                        if ((unsigned)ix < 20u) {
                            #pragma unroll
                            for (int ci = 0; ci < 3; ci++)
                                acc = fmaf(sx[ci * 400 + iy * 20 + ix],
                                           sw[c * 27 + ci * 9 + ky * 3 + kx], acc);
                        }
                    }
                }
            }
            float v = fmaxf(__fadd_rn(acc, sb[c]), 0.f);
            if (v > best) { best = v; bi = d; }   // first-max tie-break
        }
        g_p1[b * 3200 + t] = best;
        g_i1[b * 3200 + t] = (unsigned char)bi;
    }
}

// ---------------- K2: conv2(32->96,3x3,pad1)+relu+pool2x2 (640thr: 1 item) --
// smem x: [12][12][32] stride 33; w: [c][ky*3+kx][ci]. 4 out-ch x 4 positions.
__global__ void k_conv2_pool(const float* __restrict__ w, const float* __restrict__ bias)
{
    extern __shared__ float sm2[];
    float* sx = sm2;                 // 144*33 = 4752
    float* sw = sm2 + 4752;          // 27648
    float* sb = sw + 27648;          // 96
    int b = blockIdx.x;
    const float* pin = g_p1 + b * 3200;
    for (int i = threadIdx.x; i < 144 * 32; i += 640) {
        int pos = i / 32, ci = i % 32;
        int iy = pos / 12 - 1, ix = pos % 12 - 1;
        sx[pos * 33 + ci] = ((unsigned)iy < 10u && (unsigned)ix < 10u)
                          ? pin[ci * 100 + iy * 10 + ix] : 0.f;
    }
    for (int i = threadIdx.x; i < 27648; i += 640) {
        int c = i / 288, r = i % 288;
        int ci = r / 9, kk = r % 9;
        sw[c * 288 + kk * 32 + ci] = w[i];
    }
    for (int i = threadIdx.x; i < 96; i += 640) sb[i] = bias[i];
    __syncthreads();
    int t = threadIdx.x;
    if (t < 600) {
        int cg = t / 25, pp = t % 25;
        int ph = pp / 5, pw_ = pp % 5;
        float acc[4][4];
        #pragma unroll
        for (int d = 0; d < 4; d++)
            #pragma unroll
            for (int u = 0; u < 4; u++) acc[d][u] = 0.f;
        #pragma unroll
        for (int ky = 0; ky < 3; ky++) {
            #pragma unroll
            for (int kx = 0; kx < 3; kx++) {
                int base = ((2 * ph + ky) * 12 + (2 * pw_ + kx)) * 33;
                const float* wr = sw + (ky * 3 + kx) * 32;
                for (int ci = 0; ci < 32; ci++) {
                    float x0 = sx[base + ci], x1 = sx[base + 33 + ci];
                    float x2 = sx[base + 396 + ci], x3 = sx[base + 429 + ci];
                    #pragma unroll
                    for (int u = 0; u < 4; u++) {
                        float wv = wr[(cg * 4 + u) * 288 + ci];
                        acc[0][u] = fmaf(x0, wv, acc[0][u]);
                        acc[1][u] = fmaf(x1, wv, acc[1][u]);
                        acc[2][u] = fmaf(x2, wv, acc[2][u]);
                        acc[3][u] = fmaf(x3, wv, acc[3][u]);
                    }
                }
            }
        }
        #pragma unroll
        for (int u = 0; u < 4; u++) {
            int c = cg * 4 + u;
            float best = -3.4e38f; int bi = 0;
            #pragma unroll
            for (int d = 0; d < 4; d++) {
                float v = fmaxf(__fadd_rn(acc[d][u], sb[c]), 0.f);
                if (v > best) { best = v; bi = d; }
            }
            g_z [b * 2400 + c * 25 + pp] = best;
            g_i2[b * 2400 + c * 25 + pp] = (unsigned char)bi;
        }
    }
}

// ---------------- K3: pre-VQ 1x1 (800thr: 1 item; smem w transposed [c][128])
__global__ void k_pre(const float* __restrict__ w, const float* __restrict__ bias)
{
    extern __shared__ float sm3[];
    float* sz  = sm3;            // 2400
    float* swt = sm3 + 2400;     // 12288 as [c][128e]
    float* sb  = swt + 12288;    // 128
    int b = blockIdx.x;
    const float* zin = g_z + b * 2400;
    for (int i = threadIdx.x; i < 2400; i += 800) sz[i] = zin[i];
    for (int i = threadIdx.x; i < 12288; i += 800) {
        int e = i / 96, c = i % 96;
        swt[c * 128 + e] = w[i];
    }
    for (int i = threadIdx.x; i < 128; i += 800) sb[i] = bias[i];
    __syncthreads();
    int t = threadIdx.x;     // 800 threads, 800 items
    int eg = t / 25, pp = t % 25;
    float a0 = 0.f, a1 = 0.f, a2 = 0.f, a3 = 0.f;
    for (int c = 0; c < 96; c++) {
        float zv = sz[c * 25 + pp];
        float4 wq = *reinterpret_cast<const float4*>(swt + c * 128 + eg * 4);
        a0 = fmaf(zv, wq.x, a0);
        a1 = fmaf(zv, wq.y, a1);
        a2 = fmaf(zv, wq.z, a2);
        a3 = fmaf(zv, wq.w, a3);
    }
    g_vq[b * 3200 + (eg * 4 + 0) * 25 + pp] = __fadd_rn(a0, sb[eg * 4 + 0]);
    g_vq[b * 3200 + (eg * 4 + 1) * 25 + pp] = __fadd_rn(a1, sb[eg * 4 + 1]);
    g_vq[b * 3200 + (eg * 4 + 2) * 25 + pp] = __fadd_rn(a2, sb[eg * 4 + 2]);
    g_vq[b * 3200 + (eg * 4 + 3) * 25 + pp] = __fadd_rn(a3, sb[eg * 4 + 3]);
}

// ---------------- K5: VQ argmin + commit loss (rows padded to 28, LDS.128) --
// Per-token FP chain identical to R12: fn mul/add seq k; dot seq-k fma;
// d = (fn - 2*dot) + cn; first-min over ascending j.
__global__ void k_vq(const float* __restrict__ cb)
{
    extern __shared__ float sm5[];
    float* scb  = sm5;                 // 1024*28 (rows 112B, 16B-aligned)
    float* scn  = sm5 + 28672;         // 1024
    float* sred = scn + 1024;          // 512
    for (int i = threadIdx.x; i < 1024 * 28; i += 512) {
        int j = i / 28, k = i % 28;
        scb[i] = (k < 25) ? cb[j * 25 + k] : 0.f;
    }
    __syncthreads();
    // codebook norms: mul-then-add, seq ascending k
    for (int j = threadIdx.x; j < 1024; j += 512) {
        float s = 0.f;
        for (int k = 0; k < 25; k++) {
            float v = scb[j * 28 + k];
            s = __fadd_rn(s, __fmul_rn(v, v));
        }
        scn[j] = s;
    }
    __syncthreads();

    int start = (int)(((long long)blockIdx.x * 131072) / 148);
    int end   = (int)(((long long)(blockIdx.x + 1) * 131072) / 148);
    int count = end - start;                  // 885 or 886
    int tid = threadIdx.x;
    bool v0 = tid < count;
    bool v1 = tid + 512 < count;
    int t0 = start + (v0 ? tid : 0);
    int t1 = start + (v1 ? tid + 512 : 0);

    float f0[25], f1[25];
    float fn0 = 0.f, fn1 = 0.f;
    {
        const float* fp0 = g_vq + t0 * 25;
        const float* fp1 = g_vq + t1 * 25;
        #pragma unroll
        for (int k = 0; k < 25; k++) {
            float a = fp0[k], b = fp1[k];
            fn0 = __fadd_rn(fn0, __fmul_rn(a, a));
            fn1 = __fadd_rn(fn1, __fmul_rn(b, b));
            f0[k] = a; f1[k] = b;
        }
    }
    float best0 = 3.4e38f, best1 = 3.4e38f;
    int bj0 = 0, bj1 = 0;
    for (int j = 0; j < 1024; j++) {
        const float4* row = reinterpret_cast<const float4*>(scb + j * 28);
        float cw[28];
        #pragma unroll
        for (int q = 0; q < 7; q++)
            *reinterpret_cast<float4*>(cw + 4 * q) = row[q];   // LDS.128 broadcast
        float dot0 = 0.f, dot1 = 0.f;
        #pragma unroll
        for (int k = 0; k < 25; k++) {
            float cv = cw[k];
            dot0 = fmaf(cv, f0[k], dot0);   // sequential k-ascending per token
            dot1 = fmaf(cv, f1[k], dot1);
        }
        float cnj = scn[j];
        float d0 = __fadd_rn(__fsub_rn(fn0, 2.f * dot0), cnj);
        float d1 = __fadd_rn(__fsub_rn(fn1, 2.f * dot1), cnj);
        if (d0 < best0) { best0 = d0; bj0 = j; }
        if (d1 < best1) { best1 = d1; bj1 = j; }
    }
    float lsum = 0.f;
    if (v0) {
        g_ind[t0] = bj0;
        const float* fp = g_vq + t0 * 25;
        const float* cr = scb + bj0 * 28;
        #pragma unroll
        for (int k = 0; k < 25; k++) { float df = cr[k] - fp[k]; lsum = fmaf(df, df, lsum); }
    }
    if (v1) {
        g_ind[t1] = bj1;
        const float* fp = g_vq + t1 * 25;
        const float* cr = scb + bj1 * 28;
        #pragma unroll
        for (int k = 0; k < 25; k++) { float df = cr[k] - fp[k]; lsum = fmaf(df, df, lsum); }
    }
    sred[tid] = lsum;
    __syncthreads();
    for (int s = 256; s > 0; s >>= 1) {
        if (tid < s) sred[tid] += sred[tid + s];
        __syncthreads();
    }
    if (tid == 0) g_part[blockIdx.x] = sred[0];
}

// ---------------- K6: gather + 1x1 transpose-conv (640thr: 1 item, f4 w) ----
__global__ void k_trans(const float* __restrict__ cb, const float* __restrict__ w,
                        const float* __restrict__ bias)
{
    extern __shared__ float sm6[];
    float* szr = sm6;            // 128*25
    float* sw  = sm6 + 3200;     // 12288 (native [i][96], og*4 contiguous)
    float* sb  = sw + 12288;     // 96
    int b = blockIdx.x;
    for (int t = threadIdx.x; t < 3200; t += 640) {
        int i = t / 25, p = t % 25;
        szr[t] = cb[g_ind[b * 128 + i] * 25 + p];
    }
    for (int i = threadIdx.x; i < 12288; i += 640) sw[i] = w[i];
    for (int i = threadIdx.x; i < 96;    i += 640) sb[i] = bias[i];
    __syncthreads();
    int t = threadIdx.x;
    if (t < 600) {
        int og = t / 25, pp = t % 25;
        float a0 = 0.f, a1 = 0.f, a2 = 0.f, a3 = 0.f;
        for (int i = 0; i < 128; i++) {
            float zv = szr[i * 25 + pp];
            float4 wq = *reinterpret_cast<const float4*>(sw + i * 96 + og * 4);
            a0 = fmaf(zv, wq.x, a0);
            a1 = fmaf(zv, wq.y, a1);
            a2 = fmaf(zv, wq.z, a2);
            a3 = fmaf(zv, wq.w, a3);
        }
        g_lat[b * 2400 + (og * 4 + 0) * 25 + pp] = __fadd_rn(a0, sb[og * 4 + 0]);
        g_lat[b * 2400 + (og * 4 + 1) * 25 + pp] = __fadd_rn(a1, sb[og * 4 + 1]);
        g_lat[b * 2400 + (og * 4 + 2) * 25 + pp] = __fadd_rn(a2, sb[og * 4 + 2]);
        g_lat[b * 2400 + (og * 4 + 3) * 25 + pp] = __fadd_rn(a3, sb[og * 4 + 3]);
    }
}

// ---------------- K7: unpool(idx2) + dec1 conv(96->32)+relu (R12 version) ---
__global__ void k_dec1(const float* __restrict__ w, const float* __restrict__ bias)
{
    extern __shared__ float sm7[];
    float* su = sm7;             // 144*97 = 13968
    float* sw = sm7 + 13968;     // 27648
    float* sp = sw + 27648;      // 200*16 = 3200 partials
    float* sb = sp + 3200;       // 32
    int b = blockIdx.x;
    for (int i = threadIdx.x; i < 13968; i += 512) su[i] = 0.f;
    for (int i = threadIdx.x; i < 27648; i += 512) {
        int c = i / 864, r = i % 864;
        int ci = r / 9, kk = r % 9;
        sw[c * 864 + kk * 96 + ci] = w[i];
    }
    if (threadIdx.x < 32) sb[threadIdx.x] = bias[threadIdx.x];
    __syncthreads();
    for (int t = threadIdx.x; t < 2400; t += 512) {
        int c = t / 25, pp = t % 25;
        int ph = pp / 5, pw_ = pp % 5;
        int d = g_i2[b * 2400 + t];
        int y = 2 * ph + (d >> 1), x = 2 * pw_ + (d & 1);
        su[((y + 1) * 12 + (x + 1)) * 97 + c] = g_lat[b * 2400 + t];
    }
    __syncthreads();
    int tid = threadIdx.x;
    bool active = tid < 400;
    int cg = 0, win = 0, half = 0;
    float acc[4][4];
    if (active) {
        cg = tid / 50;
        int rem = tid % 50;
        half = rem / 25;
        win = rem % 25;
        int sy = win / 5, sx_ = win % 5;
        int cibase = half * 48;
        #pragma unroll
        for (int d = 0; d < 4; d++)
            #pragma unroll
            for (int u = 0; u < 4; u++) acc[d][u] = 0.f;
        #pragma unroll
        for (int ky = 0; ky < 3; ky++) {
            #pragma unroll
            for (int kx = 0; kx < 3; kx++) {
                int base = ((2 * sy + ky) * 12 + (2 * sx_ + kx)) * 97 + cibase;
                const float* wr = sw + (ky * 3 + kx) * 96 + cibase;
                for (int ci = 0; ci < 48; ci++) {
                    float x0 = su[base + ci], x1 = su[base + 97 + ci];
                    float x2 = su[base + 1164 + ci], x3 = su[base + 1261 + ci];
                    #pragma unroll
                    for (int u = 0; u < 4; u++) {
                        float wv = wr[(cg * 4 + u) * 864 + ci];
                        acc[0][u] = fmaf(x0, wv, acc[0][u]);
                        acc[1][u] = fmaf(x1, wv, acc[1][u]);
                        acc[2][u] = fmaf(x2, wv, acc[2][u]);
                        acc[3][u] = fmaf(x3, wv, acc[3][u]);
                    }
                }
            }
        }
        if (half == 1) {
            float* pp_ = sp + (cg * 25 + win) * 16;
            #pragma unroll
            for (int d = 0; d < 4; d++)
                #pragma unroll
                for (int u = 0; u < 4; u++) pp_[d * 4 + u] = acc[d][u];
        }
    }
    __syncthreads();
    if (active && half == 0) {
        int sy = win / 5, sx_ = win % 5;
        const float* pp_ = sp + (cg * 25 + win) * 16;
        #pragma unroll
        for (int d = 0; d < 4; d++) {
            int oy = 2 * sy + (d >> 1), ox = 2 * sx_ + (d & 1);
            #pragma unroll
            for (int u = 0; u < 4; u++) {
                float tot = acc[d][u] + pp_[d * 4 + u];
                g_d1[b * 3200 + (cg * 4 + u) * 100 + oy * 10 + ox] =
                    fmaxf(__fadd_rn(tot, sb[cg * 4 + u]), 0.f);
            }
        }
    }
}

// ---------------- K8: unpool(idx1) + dec2 conv(32->3) -> r_x (640thr) -------
__global__ void k_dec2(const float* __restrict__ w, const float* __restrict__ bias,
                       float* __restrict__ rx)
{
    extern __shared__ float sm8[];
    float* su = sm8;             // 484*33 = 15972
    float* sw = sm8 + 15972;     // 864
    float* sb = sw + 864;        // 3
    int b = blockIdx.x;
    for (int i = threadIdx.x; i < 15972; i += 640) su[i] = 0.f;
    for (int i = threadIdx.x; i < 864; i += 640) {
        int c = i / 288, r = i % 288;
        int ci = r / 9, kk = r % 9;
        sw[c * 288 + kk * 32 + ci] = w[i];
    }
    if (threadIdx.x < 3) sb[threadIdx.x] = bias[threadIdx.x];
    __syncthreads();
    for (int t = threadIdx.x; t < 3200; t += 640) {
        int c = t / 100, pp = t % 100;
        int ph = pp / 10, pw_ = pp % 10;
        int d = g_i1[b * 3200 + t];
        int y = 2 * ph + (d >> 1), x = 2 * pw_ + (d & 1);
        su[((y + 1) * 22 + (x + 1)) * 33 + c] = g_d1[b * 3200 + t];
    }
    __syncthreads();
    int t = threadIdx.x;
    if (t < 100) {
        int sy = t / 10, sx_ = t % 10;
        float acc[4][3];
        #pragma unroll
        for (int d = 0; d < 4; d++)
            #pragma unroll
            for (int u = 0; u < 3; u++) acc[d][u] = 0.f;
        #pragma unroll
        for (int ky = 0; ky < 3; ky++) {
            #pragma unroll
            for (int kx = 0; kx < 3; kx++) {
                int base = ((2 * sy + ky) * 22 + (2 * sx_ + kx)) * 33;
                const float* wr = sw + (ky * 3 + kx) * 32;
                for (int ci = 0; ci < 32; ci++) {
                    float x0 = su[base + ci], x1 = su[base + 33 + ci];
                    float x2 = su[base + 726 + ci], x3 = su[base + 759 + ci];
                    #pragma unroll
                    for (int u = 0; u < 3; u++) {
                        float wv = wr[u * 288 + ci];
                        acc[0][u] = fmaf(x0, wv, acc[0][u]);
                        acc[1][u] = fmaf(x1, wv, acc[1][u]);
                        acc[2][u] = fmaf(x2, wv, acc[2][u]);
                        acc[3][u] = fmaf(x3, wv, acc[3][u]);
                    }
                }
            }
        }
        #pragma unroll
        for (int d = 0; d < 4; d++) {
            int oy = 2 * sy + (d >> 1), ox = 2 * sx_ + (d & 1);
            #pragma unroll
            for (int u = 0; u < 3; u++)
                rx[b * 1200 + u * 400 + oy * 20 + ox] = __fadd_rn(acc[d][u], sb[u]);
        }
    }
}

// ---------------- K9: pose head + loss finalize -----------------------------
__global__ void k_pose(const float* __restrict__ w1, const float* __restrict__ b1,
                       const float* __restrict__ w2, const float* __restrict__ b2,
                       float* __restrict__ kp, float* __restrict__ out0)
{
    __shared__ float hid[8][32];
    __shared__ float sw2[32 * 36];
    int b0 = blockIdx.x * 8;
    int bl = threadIdx.x >> 5, j = threadIdx.x & 31;
    for (int i = threadIdx.x; i < 1152; i += 256) sw2[i] = w2[i];
    const float* fp = g_lat + (b0 + bl) * 2400;
    float a = 0.f;
    for (int k = 0; k < 2400; k++)
        a = fmaf(fp[k], w1[k * 32 + j], a);
    hid[bl][j] = fmaxf(__fadd_rn(a, b1[j]), 0.f);
    __syncthreads();
    for (int t = threadIdx.x; t < 288; t += 256) {
        int bb = t / 36, m = t % 36;
        float a2 = 0.f;
        #pragma unroll
        for (int jj = 0; jj < 32; jj++)
            a2 = fmaf(hid[bb][jj], sw2[jj * 36 + m], a2);
        kp[(b0 + bb) * 36 + m] = __fadd_rn(a2, b2[m]);
    }
    if (blockIdx.x == 0 && threadIdx.x == 0) {
        float s = 0.f;
        #pragma unroll 8
        for (int i = 0; i < 148; i++) s += g_part[i];
        out0[0] = 0.25f * s / 3276800.f;
    }
}

// ---------------- launch ----------------------------------------------------
extern "C" void kernel_launch(void* const* d_in, const int* in_sizes, int n_in,
                              void* d_out, int out_size)
{
    const float* x      = (const float*)d_in[0];
    const float* e1w    = (const float*)d_in[1];
    const float* e1b    = (const float*)d_in[2];
    const float* e2w    = (const float*)d_in[3];
    const float* e2b    = (const float*)d_in[4];
    const float* prew   = (const float*)d_in[5];
    const float* preb   = (const float*)d_in[6];
    const float* cb     = (const float*)d_in[7];
    const float* tw     = (const float*)d_in[8];
    const float* tb     = (const float*)d_in[9];
    const float* d1w    = (const float*)d_in[10];
    const float* d1b    = (const float*)d_in[11];
    const float* d2w    = (const float*)d_in[12];
    const float* d2b    = (const float*)d_in[13];
    const float* hw1    = (const float*)d_in[14];
    const float* hb1    = (const float*)d_in[15];
    const float* hw2    = (const float*)d_in[16];
    const float* hb2    = (const float*)d_in[17];
    float* out = (float*)d_out;

    const int SM2 = (4752 + 27648 + 96) * 4;              // 129984
    const int SM3 = (2400 + 12288 + 128) * 4;             // 59264
    const int SM5 = (28672 + 1024 + 512) * 4;             // 120832
    const int SM6 = (3200 + 12288 + 96) * 4;              // 62336
    const int SM7 = (13968 + 27648 + 3200 + 32) * 4;      // 179392
    const int SM8 = (15972 + 864 + 4) * 4;                // 67360

    cudaFuncSetAttribute(k_conv2_pool, cudaFuncAttributeMaxDynamicSharedMemorySize, SM2);
    cudaFuncSetAttribute(k_pre,        cudaFuncAttributeMaxDynamicSharedMemorySize, SM3);
    cudaFuncSetAttribute(k_vq,         cudaFuncAttributeMaxDynamicSharedMemorySize, SM5);
    cudaFuncSetAttribute(k_trans,      cudaFuncAttributeMaxDynamicSharedMemorySize, SM6);
    cudaFuncSetAttribute(k_dec1,       cudaFuncAttributeMaxDynamicSharedMemorySize, SM7);
    cudaFuncSetAttribute(k_dec2,       cudaFuncAttributeMaxDynamicSharedMemorySize, SM8);

    float* rx = out + 1;                 // [1024,3,20,20]
    float* kp = out + 1 + 1228800;       // [1024,36]

    k_conv1_pool<<<BATCH, 640>>>(x, e1w, e1b);
    k_conv2_pool<<<BATCH, 640, SM2>>>(e2w, e2b);
    k_pre<<<BATCH, 800, SM3>>>(prew, preb);
    k_vq<<<148, 512, SM5>>>(cb);
    k_trans<<<BATCH, 640, SM6>>>(cb, tw, tb);
    k_dec1<<<BATCH, 512, SM7>>>(d1w, d1b);
    k_dec2<<<BATCH, 640, SM8>>>(d2w, d2b, rx);
    k_pose<<<128, 256>>>(hw1, hb1, hw2, hb2, kp, out);
}

// round 17
// speedup vs baseline: 1.3982x; 1.0176x over previous
#include <cuda_runtime.h>
#include <cuda_bf16.h>

#define BATCH 1024
#define EMB 128
#define CBK 1024

// ---------------- scratch (static device globals; no runtime alloc) ----------
__device__ float         g_p1[BATCH * 32 * 100];     // pooled conv1 [b][32][10][10]
__device__ unsigned char g_i1[BATCH * 32 * 100];
__device__ float         g_z [BATCH * 96 * 25];      // pooled conv2 [b][96][5][5]
__device__ unsigned char g_i2[BATCH * 96 * 25];
__device__ float         g_vq[BATCH * EMB * 25];     // pre-VQ tokens
__device__ int           g_ind[BATCH * EMB];         // argmin indices
__device__ float         g_lat[BATCH * 96 * 25];     // latent / feat
__device__ float         g_d1[BATCH * 32 * 100];     // decoder conv1 out
__device__ float         g_part[148];                // loss partials
__device__ float         g_wc2[27648];               // conv2 w [kk][ci][96c]
__device__ float         g_wd1[27648];               // dec1  w [kk][ci][32c]

// ---------------- K0: one-off weight transpose to c-fastest -----------------
__global__ void k_prep(const float* __restrict__ w2, const float* __restrict__ wd)
{
    int i = blockIdx.x * 512 + threadIdx.x;
    if (i < 27648) {
        {   // conv2: w2[c*288 + ci*9 + kk]  ->  g_wc2[(kk*32+ci)*96 + c]
            int c = i / 288, r = i % 288;
            int ci = r / 9, kk = r % 9;
            g_wc2[(kk * 32 + ci) * 96 + c] = w2[i];
        }
        {   // dec1: wd[c*864 + ci*9 + kk]  ->  g_wd1[(kk*96+ci)*32 + c]
            int c = i / 864, r = i % 864;
            int ci = r / 9, kk = r % 9;
            g_wd1[(kk * 96 + ci) * 32 + c] = wd[i];
        }
    }
}

// ---------------- K1: conv1(3->32,3x3,pad1)+relu+pool2x2 (640thr: 5 items) --
__global__ void k_conv1_pool(const float* __restrict__ x, const float* __restrict__ w,
                             const float* __restrict__ bias)
{
    __shared__ float sx[3 * 20 * 20];
    __shared__ float sw[32 * 27];
    __shared__ float sb[32];
    int b = blockIdx.x;
    const float* xi = x + b * 1200;
    for (int i = threadIdx.x; i < 1200; i += 640) sx[i] = xi[i];
    for (int i = threadIdx.x; i < 864;  i += 640) sw[i] = w[i];
    if (threadIdx.x < 32) sb[threadIdx.x] = bias[threadIdx.x];
    __syncthreads();
    for (int t = threadIdx.x; t < 3200; t += 640) {
        int c = t / 100, pp = t % 100;
        int ph = pp / 10, pw = pp % 10;
        float best = -3.4e38f; int bi = 0;
        #pragma unroll
        for (int d = 0; d < 4; d++) {
            int oh = 2 * ph + (d >> 1), ow = 2 * pw + (d & 1);
            float acc = 0.f;
            #pragma unroll
            for (int ky = 0; ky < 3; ky++) {
                int iy = oh + ky - 1;
                if ((unsigned)iy < 20u) {
                    #pragma unroll
                    for (int kx = 0; kx < 3; kx++) {
                        int ix = ow + kx - 1;
                        if ((unsigned)ix < 20u) {
                            #pragma unroll
                            for (int ci = 0; ci < 3; ci++)
                                acc = fmaf(sx[ci * 400 + iy * 20 + ix],
                                           sw[c * 27 + ci * 9 + ky * 3 + kx], acc);
                        }
                    }
                }
            }
            float v = fmaxf(__fadd_rn(acc, sb[c]), 0.f);
            if (v > best) { best = v; bi = d; }   // first-max tie-break
        }
        g_p1[b * 3200 + t] = best;
        g_i1[b * 3200 + t] = (unsigned char)bi;
    }
}

// ---------------- K2: conv2(32->96,3x3,pad1)+relu+pool2x2 -------------------
// smem x: [12][12][32] stride 33; w linear from g_wc2 [kk][ci][96c] -> LDS.128.
__global__ void k_conv2_pool(const float* __restrict__ bias)
{
    extern __shared__ float sm2[];
    float* sx = sm2;                 // 144*33 = 4752
    float* sw = sm2 + 4752;          // 27648
    float* sb = sw + 27648;          // 96
    int b = blockIdx.x;
    const float* pin = g_p1 + b * 3200;
    for (int i = threadIdx.x; i < 144 * 32; i += 640) {
        int pos = i / 32, ci = i % 32;
        int iy = pos / 12 - 1, ix = pos % 12 - 1;
        sx[pos * 33 + ci] = ((unsigned)iy < 10u && (unsigned)ix < 10u)
                          ? pin[ci * 100 + iy * 10 + ix] : 0.f;
    }
    for (int i = threadIdx.x; i < 27648; i += 640) sw[i] = g_wc2[i];   // linear
    for (int i = threadIdx.x; i < 96; i += 640) sb[i] = bias[i];
    __syncthreads();
    int t = threadIdx.x;
    if (t < 600) {
        int cg = t / 25, pp = t % 25;
        int ph = pp / 5, pw_ = pp % 5;
        float acc[4][4];
        #pragma unroll
        for (int d = 0; d < 4; d++)
            #pragma unroll
            for (int u = 0; u < 4; u++) acc[d][u] = 0.f;
        #pragma unroll
        for (int ky = 0; ky < 3; ky++) {
            #pragma unroll
            for (int kx = 0; kx < 3; kx++) {
                int base = ((2 * ph + ky) * 12 + (2 * pw_ + kx)) * 33;
                const float* wr = sw + (ky * 3 + kx) * 32 * 96 + cg * 4;
                for (int ci = 0; ci < 32; ci++) {
                    float x0 = sx[base + ci], x1 = sx[base + 33 + ci];
                    float x2 = sx[base + 396 + ci], x3 = sx[base + 429 + ci];
                    float4 wq = *reinterpret_cast<const float4*>(wr + ci * 96);
                    acc[0][0] = fmaf(x0, wq.x, acc[0][0]);
                    acc[0][1] = fmaf(x0, wq.y, acc[0][1]);
                    acc[0][2] = fmaf(x0, wq.z, acc[0][2]);
                    acc[0][3] = fmaf(x0, wq.w, acc[0][3]);
                    acc[1][0] = fmaf(x1, wq.x, acc[1][0]);
                    acc[1][1] = fmaf(x1, wq.y, acc[1][1]);
                    acc[1][2] = fmaf(x1, wq.z, acc[1][2]);
                    acc[1][3] = fmaf(x1, wq.w, acc[1][3]);
                    acc[2][0] = fmaf(x2, wq.x, acc[2][0]);
                    acc[2][1] = fmaf(x2, wq.y, acc[2][1]);
                    acc[2][2] = fmaf(x2, wq.z, acc[2][2]);
                    acc[2][3] = fmaf(x2, wq.w, acc[2][3]);
                    acc[3][0] = fmaf(x3, wq.x, acc[3][0]);
                    acc[3][1] = fmaf(x3, wq.y, acc[3][1]);
                    acc[3][2] = fmaf(x3, wq.z, acc[3][2]);
                    acc[3][3] = fmaf(x3, wq.w, acc[3][3]);
                }
            }
        }
        #pragma unroll
        for (int u = 0; u < 4; u++) {
            int c = cg * 4 + u;
            float best = -3.4e38f; int bi = 0;
            #pragma unroll
            for (int d = 0; d < 4; d++) {
                float v = fmaxf(__fadd_rn(acc[d][u], sb[c]), 0.f);
                if (v > best) { best = v; bi = d; }
            }
            g_z [b * 2400 + c * 25 + pp] = best;
            g_i2[b * 2400 + c * 25 + pp] = (unsigned char)bi;
        }
    }
}

// ---------------- K3: pre-VQ 1x1 (800thr: 1 item; smem w transposed [c][128])
__global__ void k_pre(const float* __restrict__ w, const float* __restrict__ bias)
{
    extern __shared__ float sm3[];
    float* sz  = sm3;            // 2400
    float* swt = sm3 + 2400;     // 12288 as [c][128e]
    float* sb  = swt + 12288;    // 128
    int b = blockIdx.x;
    const float* zin = g_z + b * 2400;
    for (int i = threadIdx.x; i < 2400; i += 800) sz[i] = zin[i];
    for (int i = threadIdx.x; i < 12288; i += 800) {
        int e = i / 96, c = i % 96;
        swt[c * 128 + e] = w[i];
    }
    for (int i = threadIdx.x; i < 128; i += 800) sb[i] = bias[i];
    __syncthreads();
    int t = threadIdx.x;     // 800 threads, 800 items
    int eg = t / 25, pp = t % 25;
    float a0 = 0.f, a1 = 0.f, a2 = 0.f, a3 = 0.f;
    for (int c = 0; c < 96; c++) {
        float zv = sz[c * 25 + pp];
        float4 wq = *reinterpret_cast<const float4*>(swt + c * 128 + eg * 4);
        a0 = fmaf(zv, wq.x, a0);
        a1 = fmaf(zv, wq.y, a1);
        a2 = fmaf(zv, wq.z, a2);
        a3 = fmaf(zv, wq.w, a3);
    }
    g_vq[b * 3200 + (eg * 4 + 0) * 25 + pp] = __fadd_rn(a0, sb[eg * 4 + 0]);
    g_vq[b * 3200 + (eg * 4 + 1) * 25 + pp] = __fadd_rn(a1, sb[eg * 4 + 1]);
    g_vq[b * 3200 + (eg * 4 + 2) * 25 + pp] = __fadd_rn(a2, sb[eg * 4 + 2]);
    g_vq[b * 3200 + (eg * 4 + 3) * 25 + pp] = __fadd_rn(a3, sb[eg * 4 + 3]);
}

// ---------------- K5: VQ argmin + commit loss (rows 28, cn folded in row) ---
// Per-token FP chain identical to R16: fn mul/add seq k; dot seq-k fma;
// d = (fn - 2*dot) + cn; first-min over ascending j.
__global__ void k_vq(const float* __restrict__ cb)
{
    extern __shared__ float sm5[];
    float* scb  = sm5;                 // 1024*28 (112B rows; slot25 = cn_j)
    float* sred = sm5 + 28672;         // 512
    for (int i = threadIdx.x; i < 1024 * 28; i += 512) {
        int j = i / 28, k = i % 28;
        scb[i] = (k < 25) ? cb[j * 25 + k] : 0.f;
    }
    __syncthreads();
    // codebook norms into row slot 25: mul-then-add, seq ascending k
    for (int j = threadIdx.x; j < 1024; j += 512) {
        float s = 0.f;
        for (int k = 0; k < 25; k++) {
            float v = scb[j * 28 + k];
            s = __fadd_rn(s, __fmul_rn(v, v));
        }
        scb[j * 28 + 25] = s;
    }
    __syncthreads();

    int start = (int)(((long long)blockIdx.x * 131072) / 148);
    int end   = (int)(((long long)(blockIdx.x + 1) * 131072) / 148);
    int count = end - start;                  // 885 or 886
    int tid = threadIdx.x;
    bool v0 = tid < count;
    bool v1 = tid + 512 < count;
    int t0 = start + (v0 ? tid : 0);
    int t1 = start + (v1 ? tid + 512 : 0);

    float f0[25], f1[25];
    float fn0 = 0.f, fn1 = 0.f;
    {
        const float* fp0 = g_vq + t0 * 25;
        const float* fp1 = g_vq + t1 * 25;
        #pragma unroll
        for (int k = 0; k < 25; k++) {
            float a = fp0[k], b = fp1[k];
            fn0 = __fadd_rn(fn0, __fmul_rn(a, a));
            fn1 = __fadd_rn(fn1, __fmul_rn(b, b));
            f0[k] = a; f1[k] = b;
        }
    }
    float best0 = 3.4e38f, best1 = 3.4e38f;
    int bj0 = 0, bj1 = 0;
    const float4* row = reinterpret_cast<const float4*>(scb);
    for (int j = 0; j < 1024; j++, row += 7) {
        float cw[28];
        #pragma unroll
        for (int q = 0; q < 7; q++)
            *reinterpret_cast<float4*>(cw + 4 * q) = row[q];   // LDS.128 broadcast
        float dot0 = 0.f, dot1 = 0.f;
        #pragma unroll
        for (int k = 0; k < 25; k++) {
            float cv = cw[k];
            dot0 = fmaf(cv, f0[k], dot0);   // sequential k-ascending per token
            dot1 = fmaf(cv, f1[k], dot1);
        }
        float cnj = cw[25];
        float d0 = __fadd_rn(__fsub_rn(fn0, 2.f * dot0), cnj);
        float d1 = __fadd_rn(__fsub_rn(fn1, 2.f * dot1), cnj);
        if (d0 < best0) { best0 = d0; bj0 = j; }
        if (d1 < best1) { best1 = d1; bj1 = j; }
    }
    float lsum = 0.f;
    if (v0) {
        g_ind[t0] = bj0;
        const float* fp = g_vq + t0 * 25;
        const float* cr = scb + bj0 * 28;
        #pragma unroll
        for (int k = 0; k < 25; k++) { float df = cr[k] - fp[k]; lsum = fmaf(df, df, lsum); }
    }
    if (v1) {
        g_ind[t1] = bj1;
        const float* fp = g_vq + t1 * 25;
        const float* cr = scb + bj1 * 28;
        #pragma unroll
        for (int k = 0; k < 25; k++) { float df = cr[k] - fp[k]; lsum = fmaf(df, df, lsum); }
    }
    sred[tid] = lsum;
    __syncthreads();
    for (int s = 256; s > 0; s >>= 1) {
        if (tid < s) sred[tid] += sred[tid + s];
        __syncthreads();
    }
    if (tid == 0) g_part[blockIdx.x] = sred[0];
}

// ---------------- K6: gather + 1x1 transpose-conv (640thr: 1 item, f4 w) ----
__global__ void k_trans(const float* __restrict__ cb, const float* __restrict__ w,
                        const float* __restrict__ bias)
{
    extern __shared__ float sm6[];
    float* szr = sm6;            // 128*25
    float* sw  = sm6 + 3200;     // 12288 (native [i][96], og*4 contiguous)
    float* sb  = sw + 12288;     // 96
    int b = blockIdx.x;
    for (int t = threadIdx.x; t < 3200; t += 640) {
        int i = t / 25, p = t % 25;
        szr[t] = cb[g_ind[b * 128 + i] * 25 + p];
    }
    for (int i = threadIdx.x; i < 12288; i += 640) sw[i] = w[i];
    for (int i = threadIdx.x; i < 96;    i += 640) sb[i] = bias[i];
    __syncthreads();
    int t = threadIdx.x;
    if (t < 600) {
        int og = t / 25, pp = t % 25;
        float a0 = 0.f, a1 = 0.f, a2 = 0.f, a3 = 0.f;
        for (int i = 0; i < 128; i++) {
            float zv = szr[i * 25 + pp];
            float4 wq = *reinterpret_cast<const float4*>(sw + i * 96 + og * 4);
            a0 = fmaf(zv, wq.x, a0);
            a1 = fmaf(zv, wq.y, a1);
            a2 = fmaf(zv, wq.z, a2);
            a3 = fmaf(zv, wq.w, a3);
        }
        g_lat[b * 2400 + (og * 4 + 0) * 25 + pp] = __fadd_rn(a0, sb[og * 4 + 0]);
        g_lat[b * 2400 + (og * 4 + 1) * 25 + pp] = __fadd_rn(a1, sb[og * 4 + 1]);
        g_lat[b * 2400 + (og * 4 + 2) * 25 + pp] = __fadd_rn(a2, sb[og * 4 + 2]);
        g_lat[b * 2400 + (og * 4 + 3) * 25 + pp] = __fadd_rn(a3, sb[og * 4 + 3]);
    }
}

// ---------------- K7: unpool(idx2) + dec1 conv(96->32)+relu -----------------
// w linear from g_wd1 [kk][ci][32c] -> LDS.128; ci-halves split + smem reduce.
__global__ void k_dec1(const float* __restrict__ bias)
{
    extern __shared__ float sm7[];
    float* su = sm7;             // 144*97 = 13968
    float* sw = sm7 + 13968;     // 27648
    float* sp = sw + 27648;      // 200*16 = 3200 partials
    float* sb = sp + 3200;       // 32
    int b = blockIdx.x;
    for (int i = threadIdx.x; i < 13968; i += 512) su[i] = 0.f;
    for (int i = threadIdx.x; i < 27648; i += 512) sw[i] = g_wd1[i];   // linear
    if (threadIdx.x < 32) sb[threadIdx.x] = bias[threadIdx.x];
    __syncthreads();
    for (int t = threadIdx.x; t < 2400; t += 512) {
        int c = t / 25, pp = t % 25;
        int ph = pp / 5, pw_ = pp % 5;
        int d = g_i2[b * 2400 + t];
        int y = 2 * ph + (d >> 1), x = 2 * pw_ + (d & 1);
        su[((y + 1) * 12 + (x + 1)) * 97 + c] = g_lat[b * 2400 + t];
    }
    __syncthreads();
    int tid = threadIdx.x;
    bool active = tid < 400;
    int cg = 0, win = 0, half = 0;
    float acc[4][4];
    if (active) {
        cg = tid / 50;
        int rem = tid % 50;
        half = rem / 25;
        win = rem % 25;
        int sy = win / 5, sx_ = win % 5;
        int cibase = half * 48;
        #pragma unroll
        for (int d = 0; d < 4; d++)
            #pragma unroll
            for (int u = 0; u < 4; u++) acc[d][u] = 0.f;
        #pragma unroll
        for (int ky = 0; ky < 3; ky++) {
            #pragma unroll
            for (int kx = 0; kx < 3; kx++) {
                int base = ((2 * sy + ky) * 12 + (2 * sx_ + kx)) * 97 + cibase;
                const float* wr = sw + ((ky * 3 + kx) * 96 + cibase) * 32 + cg * 4;
                for (int ci = 0; ci < 48; ci++) {
                    float x0 = su[base + ci], x1 = su[base + 97 + ci];
                    float x2 = su[base + 1164 + ci], x3 = su[base + 1261 + ci];
                    float4 wq = *reinterpret_cast<const float4*>(wr + ci * 32);
                    acc[0][0] = fmaf(x0, wq.x, acc[0][0]);
                    acc[0][1] = fmaf(x0, wq.y, acc[0][1]);
                    acc[0][2] = fmaf(x0, wq.z, acc[0][2]);
                    acc[0][3] = fmaf(x0, wq.w, acc[0][3]);
                    acc[1][0] = fmaf(x1, wq.x, acc[1][0]);
                    acc[1][1] = fmaf(x1, wq.y, acc[1][1]);
                    acc[1][2] = fmaf(x1, wq.z, acc[1][2]);
                    acc[1][3] = fmaf(x1, wq.w, acc[1][3]);
                    acc[2][0] = fmaf(x2, wq.x, acc[2][0]);
                    acc[2][1] = fmaf(x2, wq.y, acc[2][1]);
                    acc[2][2] = fmaf(x2, wq.z, acc[2][2]);
                    acc[2][3] = fmaf(x2, wq.w, acc[2][3]);
                    acc[3][0] = fmaf(x3, wq.x, acc[3][0]);
                    acc[3][1] = fmaf(x3, wq.y, acc[3][1]);
                    acc[3][2] = fmaf(x3, wq.z, acc[3][2]);
                    acc[3][3] = fmaf(x3, wq.w, acc[3][3]);
                }
            }
        }
        if (half == 1) {
            float* pp_ = sp + (cg * 25 + win) * 16;
            #pragma unroll
            for (int d = 0; d < 4; d++)
                #pragma unroll
                for (int u = 0; u < 4; u++) pp_[d * 4 + u] = acc[d][u];
        }
    }
    __syncthreads();
    if (active && half == 0) {
        int sy = win / 5, sx_ = win % 5;
        const float* pp_ = sp + (cg * 25 + win) * 16;
        #pragma unroll
        for (int d = 0; d < 4; d++) {
            int oy = 2 * sy + (d >> 1), ox = 2 * sx_ + (d & 1);
            #pragma unroll
            for (int u = 0; u < 4; u++) {
                float tot = acc[d][u] + pp_[d * 4 + u];
                g_d1[b * 3200 + (cg * 4 + u) * 100 + oy * 10 + ox] =
                    fmaxf(__fadd_rn(tot, sb[cg * 4 + u]), 0.f);
            }
        }
    }
}

// ---------------- K8: unpool(idx1) + dec2 conv(32->3) -> r_x (640thr) -------
__global__ void k_dec2(const float* __restrict__ w, const float* __restrict__ bias,
                       float* __restrict__ rx)
{
    extern __shared__ float sm8[];
    float* su = sm8;             // 484*33 = 15972
    float* sw = sm8 + 15972;     // 864
    float* sb = sw + 864;        // 3
    int b = blockIdx.x;
    for (int i = threadIdx.x; i < 15972; i += 640) su[i] = 0.f;
    for (int i = threadIdx.x; i < 864; i += 640) {
        int c = i / 288, r = i % 288;
        int ci = r / 9, kk = r % 9;
        sw[c * 288 + kk * 32 + ci] = w[i];
    }
    if (threadIdx.x < 3) sb[threadIdx.x] = bias[threadIdx.x];
    __syncthreads();
    for (int t = threadIdx.x; t < 3200; t += 640) {
        int c = t / 100, pp = t % 100;
        int ph = pp / 10, pw_ = pp % 10;
        int d = g_i1[b * 3200 + t];
        int y = 2 * ph + (d >> 1), x = 2 * pw_ + (d & 1);
        su[((y + 1) * 22 + (x + 1)) * 33 + c] = g_d1[b * 3200 + t];
    }
    __syncthreads();
    int t = threadIdx.x;
    if (t < 100) {
        int sy = t / 10, sx_ = t % 10;
        float acc[4][3];
        #pragma unroll
        for (int d = 0; d < 4; d++)
            #pragma unroll
            for (int u = 0; u < 3; u++) acc[d][u] = 0.f;
        #pragma unroll
        for (int ky = 0; ky < 3; ky++) {
            #pragma unroll
            for (int kx = 0; kx < 3; kx++) {
                int base = ((2 * sy + ky) * 22 + (2 * sx_ + kx)) * 33;
                const float* wr = sw + (ky * 3 + kx) * 32;
                for (int ci = 0; ci < 32; ci++) {
                    float x0 = su[base + ci], x1 = su[base + 33 + ci];
                    float x2 = su[base + 726 + ci], x3 = su[base + 759 + ci];
                    #pragma unroll
                    for (int u = 0; u < 3; u++) {
                        float wv = wr[u * 288 + ci];
                        acc[0][u] = fmaf(x0, wv, acc[0][u]);
                        acc[1][u] = fmaf(x1, wv, acc[1][u]);
                        acc[2][u] = fmaf(x2, wv, acc[2][u]);
                        acc[3][u] = fmaf(x3, wv, acc[3][u]);
                    }
                }
            }
        }
        #pragma unroll
        for (int d = 0; d < 4; d++) {
            int oy = 2 * sy + (d >> 1), ox = 2 * sx_ + (d & 1);
            #pragma unroll
            for (int u = 0; u < 3; u++)
                rx[b * 1200 + u * 400 + oy * 20 + ox] = __fadd_rn(acc[d][u], sb[u]);
        }
    }
}

// ---------------- K9: pose head + loss finalize -----------------------------
__global__ void k_pose(const float* __restrict__ w1, const float* __restrict__ b1,
                       const float* __restrict__ w2, const float* __restrict__ b2,
                       float* __restrict__ kp, float* __restrict__ out0)
{
    __shared__ float hid[8][32];
    __shared__ float sw2[32 * 36];
    int b0 = blockIdx.x * 8;
    int bl = threadIdx.x >> 5, j = threadIdx.x & 31;
    for (int i = threadIdx.x; i < 1152; i += 256) sw2[i] = w2[i];
    const float* fp = g_lat + (b0 + bl) * 2400;
    float a = 0.f;
    for (int k = 0; k < 2400; k++)
        a = fmaf(fp[k], w1[k * 32 + j], a);
    hid[bl][j] = fmaxf(__fadd_rn(a, b1[j]), 0.f);
    __syncthreads();
    for (int t = threadIdx.x; t < 288; t += 256) {
        int bb = t / 36, m = t % 36;
        float a2 = 0.f;
        #pragma unroll
        for (int jj = 0; jj < 32; jj++)
            a2 = fmaf(hid[bb][jj], sw2[jj * 36 + m], a2);
        kp[(b0 + bb) * 36 + m] = __fadd_rn(a2, b2[m]);
    }
    if (blockIdx.x == 0 && threadIdx.x == 0) {
        float s = 0.f;
        #pragma unroll 8
        for (int i = 0; i < 148; i++) s += g_part[i];
        out0[0] = 0.25f * s / 3276800.f;
    }
}

// ---------------- launch ----------------------------------------------------
extern "C" void kernel_launch(void* const* d_in, const int* in_sizes, int n_in,
                              void* d_out, int out_size)
{
    const float* x      = (const float*)d_in[0];
    const float* e1w    = (const float*)d_in[1];
    const float* e1b    = (const float*)d_in[2];
    const float* e2w    = (const float*)d_in[3];
    const float* e2b    = (const float*)d_in[4];
    const float* prew   = (const float*)d_in[5];
    const float* preb   = (const float*)d_in[6];
    const float* cb     = (const float*)d_in[7];
    const float* tw     = (const float*)d_in[8];
    const float* tb     = (const float*)d_in[9];
    const float* d1w    = (const float*)d_in[10];
    const float* d1b    = (const float*)d_in[11];
    const float* d2w    = (const float*)d_in[12];
    const float* d2b    = (const float*)d_in[13];
    const float* hw1    = (const float*)d_in[14];
    const float* hb1    = (const float*)d_in[15];
    const float* hw2    = (const float*)d_in[16];
    const float* hb2    = (const float*)d_in[17];
    float* out = (float*)d_out;

    const int SM2 = (4752 + 27648 + 96) * 4;              // 129984
    const int SM3 = (2400 + 12288 + 128) * 4;             // 59264
    const int SM5 = (28672 + 512) * 4;                    // 116736
    const int SM6 = (3200 + 12288 + 96) * 4;              // 62336
    const int SM7 = (13968 + 27648 + 3200 + 32) * 4;      // 179392
    const int SM8 = (15972 + 864 + 4) * 4;                // 67360

    cudaFuncSetAttribute(k_conv2_pool, cudaFuncAttributeMaxDynamicSharedMemorySize, SM2);
    cudaFuncSetAttribute(k_pre,        cudaFuncAttributeMaxDynamicSharedMemorySize, SM3);
    cudaFuncSetAttribute(k_vq,         cudaFuncAttributeMaxDynamicSharedMemorySize, SM5);
    cudaFuncSetAttribute(k_trans,      cudaFuncAttributeMaxDynamicSharedMemorySize, SM6);
    cudaFuncSetAttribute(k_dec1,       cudaFuncAttributeMaxDynamicSharedMemorySize, SM7);
    cudaFuncSetAttribute(k_dec2,       cudaFuncAttributeMaxDynamicSharedMemorySize, SM8);

    float* rx = out + 1;                 // [1024,3,20,20]
    float* kp = out + 1 + 1228800;       // [1024,36]

    k_prep<<<54, 512>>>(e2w, d1w);
    k_conv1_pool<<<BATCH, 640>>>(x, e1w, e1b);
    k_conv2_pool<<<BATCH, 640, SM2>>>(e2b);
    k_pre<<<BATCH, 800, SM3>>>(prew, preb);
    k_vq<<<148, 512, SM5>>>(cb);
    k_trans<<<BATCH, 640, SM6>>>(cb, tw, tb);
    k_dec1<<<BATCH, 512, SM7>>>(d1b);
    k_dec2<<<BATCH, 640, SM8>>>(d2w, d2b, rx);
    k_pose<<<128, 256>>>(hw1, hb1, hw2, hb2, kp, out);
}